// round 1
// baseline (speedup 1.0000x reference)
#include <cuda_runtime.h>
#include <math.h>

#define Bb   8
#define Ss   1024
#define Dd   768
#define Hh   12
#define HDd  64
#define Ll   6
#define DFf  3072
#define Cc   2
#define Mrows (Bb*Ss)      /* 8192 */
#define QKVN  (3*Dd)       /* 2304 */
#define LN_EPS 1e-5f

// ---------------- scratch (device globals: allocation-free) ----------------
__device__ float g_x[Mrows*Dd];
__device__ float g_h[Mrows*Dd];
__device__ float g_qkv[Mrows*QKVN];
__device__ float g_att[Mrows*Dd];
__device__ float g_ff[Mrows*DFf];

// ---------------- embed: x = (tok[ids] + pos[:S]) * sqrt(D) ----------------
__global__ void embed_kernel(const int* __restrict__ ids,
                             const float* __restrict__ tok,
                             const float* __restrict__ pos,
                             float* __restrict__ x)
{
    const float sc = 27.712812921102035f; // sqrt(768)
    int i = blockIdx.x * blockDim.x + threadIdx.x;       // float4 index
    int total = Mrows * (Dd / 4);
    if (i >= total) return;
    int row = i / (Dd / 4);
    int c4  = i - row * (Dd / 4);
    int s   = row & (Ss - 1);
    int id  = ids[row];
    const float4* t4 = (const float4*)tok;
    const float4* p4 = (const float4*)pos;
    float4 tv = t4[(size_t)id * (Dd/4) + c4];
    float4 pv = p4[(size_t)s  * (Dd/4) + c4];
    float4 o;
    o.x = (tv.x + pv.x) * sc;
    o.y = (tv.y + pv.y) * sc;
    o.z = (tv.z + pv.z) * sc;
    o.w = (tv.w + pv.w) * sc;
    ((float4*)x)[i] = o;
}

// ---------------- block reduce (256 threads, 2 values) ----------------
__device__ __forceinline__ void blockReduce2(float& a, float& b, float* buf /*16 floats*/)
{
    #pragma unroll
    for (int o = 16; o; o >>= 1) {
        a += __shfl_xor_sync(0xffffffffu, a, o);
        b += __shfl_xor_sync(0xffffffffu, b, o);
    }
    int w = threadIdx.x >> 5;
    if ((threadIdx.x & 31) == 0) { buf[w] = a; buf[8 + w] = b; }
    __syncthreads();
    a = 0.f; b = 0.f;
    #pragma unroll
    for (int i = 0; i < 8; i++) { a += buf[i]; b += buf[8 + i]; }
    __syncthreads();
}

// ---------------- layernorm: out = (x-m)/sqrt(v+eps)*s + b ----------------
__global__ __launch_bounds__(256)
void ln_kernel(const float* __restrict__ x,
               const float* __restrict__ gs,
               const float* __restrict__ gb,
               float* __restrict__ out)
{
    __shared__ float buf[16];
    int row = blockIdx.x;
    int t = threadIdx.x;
    const float* xr = x + (size_t)row * Dd;
    float v0 = xr[t], v1 = xr[t + 256], v2 = xr[t + 512];
    float sum = v0 + v1 + v2;
    float sq  = v0*v0 + v1*v1 + v2*v2;
    blockReduce2(sum, sq, buf);
    float mean = sum * (1.0f / Dd);
    float var  = sq * (1.0f / Dd) - mean * mean;
    float rstd = rsqrtf(var + LN_EPS);
    float* orow = out + (size_t)row * Dd;
    orow[t]       = (v0 - mean) * rstd * gs[t]       + gb[t];
    orow[t + 256] = (v1 - mean) * rstd * gs[t + 256] + gb[t + 256];
    orow[t + 512] = (v2 - mean) * rstd * gs[t + 512] + gb[t + 512];
}

// ---------------- GEMM: C = A[M,K] @ W[K,N] + bias (+res) (relu?) ----------
// BM=BN=128, BK=8, 256 threads, 8x8 per-thread microtile.
__global__ __launch_bounds__(256)
void gemm_kernel(const float* __restrict__ A,
                 const float* __restrict__ W,
                 const float* __restrict__ bias,
                 const float* __restrict__ res,
                 float* __restrict__ C,
                 int K, int N, int relu)
{
    __shared__ float As[8][128];
    __shared__ float Bs[8][128];

    int tid = threadIdx.x;
    int bx = blockIdx.x;     // N tile
    int by = blockIdx.y;     // M tile

    int tm = (tid >> 4) * 8; // 0..120
    int tn = (tid & 15) * 8; // 0..120

    int aRow = tid >> 1;          // 0..127
    int aCol = (tid & 1) * 4;     // 0 or 4
    int bRow = tid >> 5;          // 0..7
    int bCol = (tid & 31) * 4;    // 0..124

    const float* Ab = A + (size_t)(by * 128 + aRow) * K + aCol;
    const float* Wb = W + (size_t)bRow * N + bx * 128 + bCol;

    float acc[8][8];
    #pragma unroll
    for (int i = 0; i < 8; i++)
        #pragma unroll
        for (int j = 0; j < 8; j++) acc[i][j] = 0.f;

    for (int k0 = 0; k0 < K; k0 += 8) {
        float4 av = *(const float4*)(Ab + k0);
        As[aCol + 0][aRow] = av.x;
        As[aCol + 1][aRow] = av.y;
        As[aCol + 2][aRow] = av.z;
        As[aCol + 3][aRow] = av.w;
        float4 bv = *(const float4*)(Wb + (size_t)k0 * N);
        *(float4*)&Bs[bRow][bCol] = bv;
        __syncthreads();

        #pragma unroll
        for (int k = 0; k < 8; k++) {
            float a[8], b[8];
            #pragma unroll
            for (int i = 0; i < 8; i++) a[i] = As[k][tm + i];
            #pragma unroll
            for (int j = 0; j < 8; j++) b[j] = Bs[k][tn + j];
            #pragma unroll
            for (int i = 0; i < 8; i++)
                #pragma unroll
                for (int j = 0; j < 8; j++)
                    acc[i][j] += a[i] * b[j];
        }
        __syncthreads();
    }

    #pragma unroll
    for (int i = 0; i < 8; i++) {
        int row = by * 128 + tm + i;
        #pragma unroll
        for (int j = 0; j < 8; j++) {
            int col = bx * 128 + tn + j;
            float v = acc[i][j] + bias[col];
            if (res) v += res[(size_t)row * N + col];
            if (relu) v = fmaxf(v, 0.f);
            C[(size_t)row * N + col] = v;
        }
    }
}

// ---------------- flash attention ----------------
// grid (S/128, H, B); 128 threads; thread owns one q-row.
// qkv layout per row: [h][{q,k,v}][hd] -> col = h*192 + which*64 + hd
#define ATT_SMEM ((128*65 + 64*64 + 64*64 + 64) * 4)

__global__ __launch_bounds__(128, 1)
void attn_kernel(const float* __restrict__ qkv,
                 const int* __restrict__ mask,
                 float* __restrict__ att)
{
    extern __shared__ float sm[];
    float* qs = sm;                 // [128][65] padded
    float* kT = qs + 128 * 65;      // [64][64] transposed keys
    float* vs = kT + 64 * 64;       // [64][64]
    float* mk = vs + 64 * 64;       // [64]

    int qb = blockIdx.x, h = blockIdx.y, b = blockIdx.z;
    int tid = threadIdx.x;
    int base_q = b * Ss + qb * 128;

    // load q tile (coalesced-ish float4)
    const float* qsrc = qkv + (size_t)base_q * QKVN + h * 192;
    #pragma unroll
    for (int it = 0; it < 16; it++) {
        int idx = it * 128 + tid;
        int r = idx >> 4, c4 = idx & 15;
        float4 v = *(const float4*)(qsrc + (size_t)r * QKVN + c4 * 4);
        float* dst = qs + r * 65 + c4 * 4;
        dst[0] = v.x; dst[1] = v.y; dst[2] = v.z; dst[3] = v.w;
    }
    __syncthreads();

    float acc[64];
    float s[64];
    #pragma unroll
    for (int d = 0; d < 64; d++) acc[d] = 0.f;
    float mrun = -1e30f, lrun = 0.f;
    const float* qrow = qs + tid * 65;

    for (int kt = 0; kt < Ss / 64; kt++) {
        const float* ksrc = qkv + (size_t)(b * Ss + kt * 64) * QKVN + h * 192 + 64;
        const float* vsrc = ksrc + 64;
        #pragma unroll
        for (int it = 0; it < 8; it++) {
            int idx = it * 128 + tid;
            int r = idx >> 4, c4 = idx & 15;
            float4 kv = *(const float4*)(ksrc + (size_t)r * QKVN + c4 * 4);
            kT[(c4 * 4 + 0) * 64 + r] = kv.x;
            kT[(c4 * 4 + 1) * 64 + r] = kv.y;
            kT[(c4 * 4 + 2) * 64 + r] = kv.z;
            kT[(c4 * 4 + 3) * 64 + r] = kv.w;
            float4 vv = *(const float4*)(vsrc + (size_t)r * QKVN + c4 * 4);
            *(float4*)(vs + r * 64 + c4 * 4) = vv;
        }
        if (tid < 64) mk[tid] = (mask[b * Ss + kt * 64 + tid] != 0) ? 1.f : 0.f;
        __syncthreads();

        // scores: s[j] = q . k_j
        #pragma unroll
        for (int j = 0; j < 64; j++) s[j] = 0.f;
        #pragma unroll 4
        for (int d = 0; d < 64; d++) {
            float qv = qrow[d];
            const float4* krow = (const float4*)(kT + d * 64);
            #pragma unroll
            for (int j4 = 0; j4 < 16; j4++) {
                float4 kk = krow[j4];
                s[j4 * 4 + 0] += qv * kk.x;
                s[j4 * 4 + 1] += qv * kk.y;
                s[j4 * 4 + 2] += qv * kk.z;
                s[j4 * 4 + 3] += qv * kk.w;
            }
        }

        // reference's inverted mask: positions with mask==1 get exactly -1e9
        float mx = mrun;
        #pragma unroll
        for (int j = 0; j < 64; j++) {
            float sv = (mk[j] != 0.f) ? -1e9f : s[j] * 0.125f;
            s[j] = sv;
            mx = fmaxf(mx, sv);
        }
        float corr = __expf(mrun - mx);
        mrun = mx;
        lrun *= corr;
        #pragma unroll
        for (int d = 0; d < 64; d++) acc[d] *= corr;
        #pragma unroll
        for (int j = 0; j < 64; j++) {
            float p = __expf(s[j] - mx);
            s[j] = p;
            lrun += p;
        }

        // acc += p @ V
        #pragma unroll
        for (int j = 0; j < 64; j++) {
            float p = s[j];
            const float4* vrow = (const float4*)(vs + j * 64);
            #pragma unroll
            for (int d4 = 0; d4 < 16; d4++) {
                float4 vv = vrow[d4];
                acc[d4 * 4 + 0] += p * vv.x;
                acc[d4 * 4 + 1] += p * vv.y;
                acc[d4 * 4 + 2] += p * vv.z;
                acc[d4 * 4 + 3] += p * vv.w;
            }
        }
        __syncthreads();
    }

    float inv = 1.f / lrun;
    float* dst = att + (size_t)(base_q + tid) * Dd + h * HDd;
    #pragma unroll
    for (int d4 = 0; d4 < 16; d4++) {
        float4 o;
        o.x = acc[d4 * 4 + 0] * inv;
        o.y = acc[d4 * 4 + 1] * inv;
        o.z = acc[d4 * 4 + 2] * inv;
        o.w = acc[d4 * 4 + 3] * inv;
        *(float4*)(dst + d4 * 4) = o;
    }
}

// ---------------- pooled LN + classifier ----------------
__global__ __launch_bounds__(256)
void pooled_kernel(const float* __restrict__ x,
                   const float* __restrict__ hs,
                   const float* __restrict__ hb,
                   const float* __restrict__ cw,
                   const float* __restrict__ cb,
                   float* __restrict__ out)
{
    __shared__ float buf[16];
    int b = blockIdx.x;
    int t = threadIdx.x;
    const float* xr = x + (size_t)b * Ss * Dd;  // row s=0
    float v0 = xr[t], v1 = xr[t + 256], v2 = xr[t + 512];
    float sum = v0 + v1 + v2;
    float sq  = v0*v0 + v1*v1 + v2*v2;
    blockReduce2(sum, sq, buf);
    float mean = sum * (1.0f / Dd);
    float var  = sq * (1.0f / Dd) - mean * mean;
    float rstd = rsqrtf(var + LN_EPS);
    float h0 = (v0 - mean) * rstd * hs[t]       + hb[t];
    float h1 = (v1 - mean) * rstd * hs[t + 256] + hb[t + 256];
    float h2 = (v2 - mean) * rstd * hs[t + 512] + hb[t + 512];
    float p0 = h0 * cw[t * 2]           + h1 * cw[(t + 256) * 2]     + h2 * cw[(t + 512) * 2];
    float p1 = h0 * cw[t * 2 + 1]       + h1 * cw[(t + 256) * 2 + 1] + h2 * cw[(t + 512) * 2 + 1];
    blockReduce2(p0, p1, buf);
    if (t == 0) {
        out[b * Cc + 0] = p0 + cb[0];
        out[b * Cc + 1] = p1 + cb[1];
    }
}

// ---------------- launcher ----------------
extern "C" void kernel_launch(void* const* d_in, const int* in_sizes, int n_in,
                              void* d_out, int out_size)
{
    const int*   ids    = (const int*)  d_in[0];
    const int*   mask   = (const int*)  d_in[1];
    const float* tok    = (const float*)d_in[2];
    const float* pos    = (const float*)d_in[3];
    const float* qkv_w  = (const float*)d_in[4];
    const float* qkv_b  = (const float*)d_in[5];
    const float* out_w  = (const float*)d_in[6];
    const float* out_b  = (const float*)d_in[7];
    const float* n1_s   = (const float*)d_in[8];
    const float* n1_b   = (const float*)d_in[9];
    const float* ff1_w  = (const float*)d_in[10];
    const float* ff1_b  = (const float*)d_in[11];
    const float* ff2_w  = (const float*)d_in[12];
    const float* ff2_b  = (const float*)d_in[13];
    const float* n2_s   = (const float*)d_in[14];
    const float* n2_b   = (const float*)d_in[15];
    const float* hln_s  = (const float*)d_in[16];
    const float* hln_b  = (const float*)d_in[17];
    const float* cls_w  = (const float*)d_in[18];
    const float* cls_b  = (const float*)d_in[19];
    float* out = (float*)d_out;

    float *x, *h, *qkvb, *attb, *ffb;
    cudaGetSymbolAddress((void**)&x,    g_x);
    cudaGetSymbolAddress((void**)&h,    g_h);
    cudaGetSymbolAddress((void**)&qkvb, g_qkv);
    cudaGetSymbolAddress((void**)&attb, g_att);
    cudaGetSymbolAddress((void**)&ffb,  g_ff);

    cudaFuncSetAttribute(attn_kernel, cudaFuncAttributeMaxDynamicSharedMemorySize, ATT_SMEM);

    int embed_total = Mrows * (Dd / 4);
    embed_kernel<<<(embed_total + 255) / 256, 256>>>(ids, tok, pos, x);

    for (int i = 0; i < Ll; i++) {
        ln_kernel<<<Mrows, 256>>>(x, n1_s + i * Dd, n1_b + i * Dd, h);

        gemm_kernel<<<dim3(QKVN / 128, Mrows / 128), 256>>>(
            h, qkv_w + (size_t)i * Dd * QKVN, qkv_b + (size_t)i * QKVN,
            nullptr, qkvb, Dd, QKVN, 0);

        attn_kernel<<<dim3(Ss / 128, Hh, Bb), 128, ATT_SMEM>>>(qkvb, mask, attb);

        gemm_kernel<<<dim3(Dd / 128, Mrows / 128), 256>>>(
            attb, out_w + (size_t)i * Dd * Dd, out_b + (size_t)i * Dd,
            x, x, Dd, Dd, 0);

        ln_kernel<<<Mrows, 256>>>(x, n2_s + i * Dd, n2_b + i * Dd, h);

        gemm_kernel<<<dim3(DFf / 128, Mrows / 128), 256>>>(
            h, ff1_w + (size_t)i * Dd * DFf, ff1_b + (size_t)i * DFf,
            nullptr, ffb, Dd, DFf, 1);

        gemm_kernel<<<dim3(Dd / 128, Mrows / 128), 256>>>(
            ffb, ff2_w + (size_t)i * DFf * Dd, ff2_b + (size_t)i * Dd,
            x, x, DFf, Dd, 0);
    }

    pooled_kernel<<<Bb, 256>>>(x, hln_s, hln_b, cls_w, cls_b, out);
}

// round 3
// speedup vs baseline: 1.8484x; 1.8484x over previous
#include <cuda_runtime.h>
#include <cstdint>
#include <math.h>

#define Bb   8
#define Ss   1024
#define Dd   768
#define Hh   12
#define HDd  64
#define Ll   6
#define DFf  3072
#define Cc   2
#define Mrows (Bb*Ss)      /* 8192 */
#define QKVN  (3*Dd)       /* 2304 */
#define LN_EPS 1e-5f

// ---------------- scratch (device globals: allocation-free) ----------------
__device__ float g_x[Mrows*Dd];
__device__ float g_h[Mrows*Dd];
__device__ float g_qkv[Mrows*QKVN];
__device__ float g_att[Mrows*Dd];
__device__ float g_ff[Mrows*DFf];
__device__ float g_wt[DFf*Dd];     // transposed weight scratch (max 3072*768)

// ======================= helpers =======================
__device__ __forceinline__ uint32_t smem_to_u32(const void* p) {
    uint32_t a;
    asm("{ .reg .u64 t; cvta.to.shared.u64 t, %1; cvt.u32.u64 %0, t; }" : "=r"(a) : "l"(p));
    return a;
}
__device__ __forceinline__ float rna_tf32(float v) {
    asm("cvt.rna.tf32.f32 %0, %0;" : "+f"(v));
    return v;
}
#define CP_ASYNC16(dst, src) \
    asm volatile("cp.async.cg.shared.global [%0], [%1], 16;" :: "r"(dst), "l"(src) : "memory")
#define CP_COMMIT() asm volatile("cp.async.commit_group;" ::: "memory")
#define CP_WAIT1()  asm volatile("cp.async.wait_group 1;" ::: "memory")

__device__ __forceinline__ void mma_tf32(float* d, const uint32_t* a, const uint32_t* b) {
    asm volatile(
        "mma.sync.aligned.m16n8k8.row.col.f32.tf32.tf32.f32 "
        "{%0,%1,%2,%3}, {%4,%5,%6,%7}, {%8,%9}, {%0,%1,%2,%3};"
        : "+f"(d[0]), "+f"(d[1]), "+f"(d[2]), "+f"(d[3])
        : "r"(a[0]), "r"(a[1]), "r"(a[2]), "r"(a[3]), "r"(b[0]), "r"(b[1]));
}

// ---------------- embed ----------------
__global__ void embed_kernel(const int* __restrict__ ids,
                             const float* __restrict__ tok,
                             const float* __restrict__ pos,
                             float* __restrict__ x)
{
    const float sc = 27.712812921102035f; // sqrt(768)
    int i = blockIdx.x * blockDim.x + threadIdx.x;
    int total = Mrows * (Dd / 4);
    if (i >= total) return;
    int row = i / (Dd / 4);
    int c4  = i - row * (Dd / 4);
    int s   = row & (Ss - 1);
    int id  = ids[row];
    const float4* t4 = (const float4*)tok;
    const float4* p4 = (const float4*)pos;
    float4 tv = t4[(size_t)id * (Dd/4) + c4];
    float4 pv = p4[(size_t)s  * (Dd/4) + c4];
    float4 o;
    o.x = (tv.x + pv.x) * sc;
    o.y = (tv.y + pv.y) * sc;
    o.z = (tv.z + pv.z) * sc;
    o.w = (tv.w + pv.w) * sc;
    ((float4*)x)[i] = o;
}

// ---------------- block reduce ----------------
__device__ __forceinline__ void blockReduce2(float& a, float& b, float* buf)
{
    #pragma unroll
    for (int o = 16; o; o >>= 1) {
        a += __shfl_xor_sync(0xffffffffu, a, o);
        b += __shfl_xor_sync(0xffffffffu, b, o);
    }
    int w = threadIdx.x >> 5;
    if ((threadIdx.x & 31) == 0) { buf[w] = a; buf[8 + w] = b; }
    __syncthreads();
    a = 0.f; b = 0.f;
    #pragma unroll
    for (int i = 0; i < 8; i++) { a += buf[i]; b += buf[8 + i]; }
    __syncthreads();
}

// ---------------- layernorm (outputs RNA-rounded to tf32: feeds GEMM A) ----
__global__ __launch_bounds__(256)
void ln_kernel(const float* __restrict__ x,
               const float* __restrict__ gs,
               const float* __restrict__ gb,
               float* __restrict__ out)
{
    __shared__ float buf[16];
    int row = blockIdx.x;
    int t = threadIdx.x;
    const float* xr = x + (size_t)row * Dd;
    float v0 = xr[t], v1 = xr[t + 256], v2 = xr[t + 512];
    float sum = v0 + v1 + v2;
    float sq  = v0*v0 + v1*v1 + v2*v2;
    blockReduce2(sum, sq, buf);
    float mean = sum * (1.0f / Dd);
    float var  = sq * (1.0f / Dd) - mean * mean;
    float rstd = rsqrtf(var + LN_EPS);
    float* orow = out + (size_t)row * Dd;
    orow[t]       = rna_tf32((v0 - mean) * rstd * gs[t]       + gb[t]);
    orow[t + 256] = rna_tf32((v1 - mean) * rstd * gs[t + 256] + gb[t + 256]);
    orow[t + 512] = rna_tf32((v2 - mean) * rstd * gs[t + 512] + gb[t + 512]);
}

// ---------------- weight transpose + RNA round: Wt[N,K] = rna(W[K,N]^T) ----
__global__ __launch_bounds__(256)
void transpose_rna_kernel(const float* __restrict__ W, float* __restrict__ Wt, int K, int N)
{
    __shared__ float t[32][33];
    int n0 = blockIdx.x * 32, k0 = blockIdx.y * 32;
    int x = threadIdx.x & 31, y = threadIdx.x >> 5; // 32x8
    #pragma unroll
    for (int i = 0; i < 32; i += 8)
        t[y + i][x] = W[(size_t)(k0 + y + i) * N + n0 + x];
    __syncthreads();
    #pragma unroll
    for (int i = 0; i < 32; i += 8)
        Wt[(size_t)(n0 + y + i) * K + k0 + x] = rna_tf32(t[x][y + i]);
}

// ---------------- tf32 mma.sync GEMM ----------------
// C[M,N] = A[M,K] @ Bt[N,K]^T (+bias)(+res)(relu?)(rnaOut?)
// BM=BN=128, BK=32, 256 threads, warp grid 2x4 (warp tile 64x32),
// 3-stage cp.async pipeline, SMEM rows padded to 36 floats (16B-aligned, no
// bank conflicts on fragment loads: bank = (4r+c) mod 32 = lane).
#define TSf (128*36)                 /* floats per tile */
#define GEMM_SMEM (3*2*TSf*4)        /* 110592 bytes */

__global__ __launch_bounds__(256, 1)
void mma_gemm(const float* __restrict__ A, const float* __restrict__ Bt,
              const float* __restrict__ bias, const float* __restrict__ res,
              float* __restrict__ C, int K, int N, int relu, int rnaOut)
{
    extern __shared__ float smf[];
    uint32_t sb = smem_to_u32(smf);
    int tid = threadIdx.x, lane = tid & 31, wid = tid >> 5;
    int warpM = (wid >> 2) * 64, warpN = (wid & 3) * 32;
    int m0 = blockIdx.y * 128, n0 = blockIdx.x * 128;
    const float* Abase = A  + (size_t)m0 * K;
    const float* Bbase = Bt + (size_t)n0 * K;
    int lrow  = tid >> 1;        // 0..127
    int lhalf = (tid & 1) * 16;  // float offset within a 32-float row

    const int KI = K >> 5;

    float acc[4][4][4];
    #pragma unroll
    for (int mt = 0; mt < 4; mt++)
        #pragma unroll
        for (int nt = 0; nt < 4; nt++)
            #pragma unroll
            for (int r = 0; r < 4; r++) acc[mt][nt][r] = 0.f;

    // stage issue
    #define ISSUE_STAGE(I) do {                                                  \
        int _st = (I) % 3;                                                       \
        int _k0 = (I) << 5;                                                      \
        uint32_t _dA = sb + (uint32_t)(_st * 2 * TSf + lrow * 36 + lhalf) * 4u;  \
        uint32_t _dB = _dA + (uint32_t)TSf * 4u;                                 \
        const float* _sA = Abase + (size_t)lrow * K + _k0 + lhalf;               \
        const float* _sB = Bbase + (size_t)lrow * K + _k0 + lhalf;               \
        CP_ASYNC16(_dA + 0,  _sA + 0);  CP_ASYNC16(_dB + 0,  _sB + 0);           \
        CP_ASYNC16(_dA + 16, _sA + 4);  CP_ASYNC16(_dB + 16, _sB + 4);           \
        CP_ASYNC16(_dA + 32, _sA + 8);  CP_ASYNC16(_dB + 32, _sB + 8);           \
        CP_ASYNC16(_dA + 48, _sA + 12); CP_ASYNC16(_dB + 48, _sB + 12);          \
    } while (0)

    ISSUE_STAGE(0); CP_COMMIT();
    ISSUE_STAGE(1); CP_COMMIT();

    for (int i = 0; i < KI; i++) {
        CP_WAIT1();
        __syncthreads();
        if (i + 2 < KI) ISSUE_STAGE(i + 2);
        CP_COMMIT();

        const float* As = smf + (i % 3) * 2 * TSf;
        const float* Bs = As + TSf;

        #pragma unroll
        for (int ks = 0; ks < 4; ks++) {
            int kc = ks * 8 + (lane & 3);
            uint32_t a[4][4], b[4][2];
            #pragma unroll
            for (int mt = 0; mt < 4; mt++) {
                int r = warpM + mt * 16 + (lane >> 2);
                a[mt][0] = __float_as_uint(As[r * 36 + kc]);
                a[mt][1] = __float_as_uint(As[(r + 8) * 36 + kc]);
                a[mt][2] = __float_as_uint(As[r * 36 + kc + 4]);
                a[mt][3] = __float_as_uint(As[(r + 8) * 36 + kc + 4]);
            }
            #pragma unroll
            for (int nt = 0; nt < 4; nt++) {
                int n = warpN + nt * 8 + (lane >> 2);
                b[nt][0] = __float_as_uint(Bs[n * 36 + kc]);
                b[nt][1] = __float_as_uint(Bs[n * 36 + kc + 4]);
            }
            #pragma unroll
            for (int mt = 0; mt < 4; mt++)
                #pragma unroll
                for (int nt = 0; nt < 4; nt++)
                    mma_tf32(acc[mt][nt], a[mt], b[nt]);
        }
    }

    // epilogue
    #pragma unroll
    for (int mt = 0; mt < 4; mt++) {
        int r0 = m0 + warpM + mt * 16 + (lane >> 2);
        #pragma unroll
        for (int nt = 0; nt < 4; nt++) {
            int c0 = n0 + warpN + nt * 8 + (lane & 3) * 2;
            float2 bv = *(const float2*)(bias + c0);
            float v0 = acc[mt][nt][0] + bv.x;
            float v1 = acc[mt][nt][1] + bv.y;
            float v2 = acc[mt][nt][2] + bv.x;
            float v3 = acc[mt][nt][3] + bv.y;
            if (res) {
                float2 q1 = *(const float2*)(res + (size_t)r0 * N + c0);
                float2 q2 = *(const float2*)(res + (size_t)(r0 + 8) * N + c0);
                v0 += q1.x; v1 += q1.y; v2 += q2.x; v3 += q2.y;
            }
            if (relu) {
                v0 = fmaxf(v0, 0.f); v1 = fmaxf(v1, 0.f);
                v2 = fmaxf(v2, 0.f); v3 = fmaxf(v3, 0.f);
            }
            if (rnaOut) {
                v0 = rna_tf32(v0); v1 = rna_tf32(v1);
                v2 = rna_tf32(v2); v3 = rna_tf32(v3);
            }
            float2 o1; o1.x = v0; o1.y = v1;
            float2 o2; o2.x = v2; o2.y = v3;
            *(float2*)(C + (size_t)r0 * N + c0)       = o1;
            *(float2*)(C + (size_t)(r0 + 8) * N + c0) = o2;
        }
    }
}

// ---------------- flash attention (fp32; output RNA-rounded: feeds GEMM A) --
#define ATT_SMEM ((128*65 + 64*64 + 64*64 + 64) * 4)

__global__ __launch_bounds__(128, 2)
void attn_kernel(const float* __restrict__ qkv,
                 const int* __restrict__ mask,
                 float* __restrict__ att)
{
    extern __shared__ float smfa[];
    float* qs = smfa;               // [128][65] padded
    float* kT = qs + 128 * 65;      // [64][64] transposed keys
    float* vs = kT + 64 * 64;       // [64][64]
    float* mk = vs + 64 * 64;       // [64]

    int qb = blockIdx.x, h = blockIdx.y, b = blockIdx.z;
    int tid = threadIdx.x;
    int base_q = b * Ss + qb * 128;

    const float* qsrc = qkv + (size_t)base_q * QKVN + h * 192;
    #pragma unroll
    for (int it = 0; it < 16; it++) {
        int idx = it * 128 + tid;
        int r = idx >> 4, c4 = idx & 15;
        float4 v = *(const float4*)(qsrc + (size_t)r * QKVN + c4 * 4);
        float* dst = qs + r * 65 + c4 * 4;
        dst[0] = v.x; dst[1] = v.y; dst[2] = v.z; dst[3] = v.w;
    }
    __syncthreads();

    float acc[64];
    float s[64];
    #pragma unroll
    for (int d = 0; d < 64; d++) acc[d] = 0.f;
    float mrun = -1e30f, lrun = 0.f;
    const float* qrow = qs + tid * 65;

    for (int kt = 0; kt < Ss / 64; kt++) {
        const float* ksrc = qkv + (size_t)(b * Ss + kt * 64) * QKVN + h * 192 + 64;
        const float* vsrc = ksrc + 64;
        #pragma unroll
        for (int it = 0; it < 8; it++) {
            int idx = it * 128 + tid;
            int r = idx >> 4, c4 = idx & 15;
            float4 kv = *(const float4*)(ksrc + (size_t)r * QKVN + c4 * 4);
            kT[(c4 * 4 + 0) * 64 + r] = kv.x;
            kT[(c4 * 4 + 1) * 64 + r] = kv.y;
            kT[(c4 * 4 + 2) * 64 + r] = kv.z;
            kT[(c4 * 4 + 3) * 64 + r] = kv.w;
            float4 vv = *(const float4*)(vsrc + (size_t)r * QKVN + c4 * 4);
            *(float4*)(vs + r * 64 + c4 * 4) = vv;
        }
        if (tid < 64) mk[tid] = (mask[b * Ss + kt * 64 + tid] != 0) ? 1.f : 0.f;
        __syncthreads();

        #pragma unroll
        for (int j = 0; j < 64; j++) s[j] = 0.f;
        #pragma unroll 4
        for (int d = 0; d < 64; d++) {
            float qv = qrow[d];
            const float4* krow = (const float4*)(kT + d * 64);
            #pragma unroll
            for (int j4 = 0; j4 < 16; j4++) {
                float4 kk = krow[j4];
                s[j4 * 4 + 0] += qv * kk.x;
                s[j4 * 4 + 1] += qv * kk.y;
                s[j4 * 4 + 2] += qv * kk.z;
                s[j4 * 4 + 3] += qv * kk.w;
            }
        }

        float mx = mrun;
        #pragma unroll
        for (int j = 0; j < 64; j++) {
            float sv = (mk[j] != 0.f) ? -1e9f : s[j] * 0.125f;
            s[j] = sv;
            mx = fmaxf(mx, sv);
        }
        float corr = __expf(mrun - mx);
        mrun = mx;
        lrun *= corr;
        #pragma unroll
        for (int d = 0; d < 64; d++) acc[d] *= corr;
        #pragma unroll
        for (int j = 0; j < 64; j++) {
            float p = __expf(s[j] - mx);
            s[j] = p;
            lrun += p;
        }

        #pragma unroll
        for (int j = 0; j < 64; j++) {
            float p = s[j];
            const float4* vrow = (const float4*)(vs + j * 64);
            #pragma unroll
            for (int d4 = 0; d4 < 16; d4++) {
                float4 vv = vrow[d4];
                acc[d4 * 4 + 0] += p * vv.x;
                acc[d4 * 4 + 1] += p * vv.y;
                acc[d4 * 4 + 2] += p * vv.z;
                acc[d4 * 4 + 3] += p * vv.w;
            }
        }
        __syncthreads();
    }

    float inv = 1.f / lrun;
    float* dst = att + (size_t)(base_q + tid) * Dd + h * HDd;
    #pragma unroll
    for (int d4 = 0; d4 < 16; d4++) {
        float4 o;
        o.x = rna_tf32(acc[d4 * 4 + 0] * inv);
        o.y = rna_tf32(acc[d4 * 4 + 1] * inv);
        o.z = rna_tf32(acc[d4 * 4 + 2] * inv);
        o.w = rna_tf32(acc[d4 * 4 + 3] * inv);
        *(float4*)(dst + d4 * 4) = o;
    }
}

// ---------------- pooled LN + classifier ----------------
__global__ __launch_bounds__(256)
void pooled_kernel(const float* __restrict__ x,
                   const float* __restrict__ hs,
                   const float* __restrict__ hb,
                   const float* __restrict__ cw,
                   const float* __restrict__ cb,
                   float* __restrict__ out)
{
    __shared__ float buf[16];
    int b = blockIdx.x;
    int t = threadIdx.x;
    const float* xr = x + (size_t)b * Ss * Dd;
    float v0 = xr[t], v1 = xr[t + 256], v2 = xr[t + 512];
    float sum = v0 + v1 + v2;
    float sq  = v0*v0 + v1*v1 + v2*v2;
    blockReduce2(sum, sq, buf);
    float mean = sum * (1.0f / Dd);
    float var  = sq * (1.0f / Dd) - mean * mean;
    float rstd = rsqrtf(var + LN_EPS);
    float h0 = (v0 - mean) * rstd * hs[t]       + hb[t];
    float h1 = (v1 - mean) * rstd * hs[t + 256] + hb[t + 256];
    float h2 = (v2 - mean) * rstd * hs[t + 512] + hb[t + 512];
    float p0 = h0 * cw[t * 2]     + h1 * cw[(t + 256) * 2]     + h2 * cw[(t + 512) * 2];
    float p1 = h0 * cw[t * 2 + 1] + h1 * cw[(t + 256) * 2 + 1] + h2 * cw[(t + 512) * 2 + 1];
    blockReduce2(p0, p1, buf);
    if (t == 0) {
        out[b * Cc + 0] = p0 + cb[0];
        out[b * Cc + 1] = p1 + cb[1];
    }
}

// ---------------- launcher ----------------
extern "C" void kernel_launch(void* const* d_in, const int* in_sizes, int n_in,
                              void* d_out, int out_size)
{
    const int*   ids    = (const int*)  d_in[0];
    const int*   mask   = (const int*)  d_in[1];
    const float* tok    = (const float*)d_in[2];
    const float* pos    = (const float*)d_in[3];
    const float* qkv_w  = (const float*)d_in[4];
    const float* qkv_b  = (const float*)d_in[5];
    const float* out_w  = (const float*)d_in[6];
    const float* out_b  = (const float*)d_in[7];
    const float* n1_s   = (const float*)d_in[8];
    const float* n1_b   = (const float*)d_in[9];
    const float* ff1_w  = (const float*)d_in[10];
    const float* ff1_b  = (const float*)d_in[11];
    const float* ff2_w  = (const float*)d_in[12];
    const float* ff2_b  = (const float*)d_in[13];
    const float* n2_s   = (const float*)d_in[14];
    const float* n2_b   = (const float*)d_in[15];
    const float* hln_s  = (const float*)d_in[16];
    const float* hln_b  = (const float*)d_in[17];
    const float* cls_w  = (const float*)d_in[18];
    const float* cls_b  = (const float*)d_in[19];
    float* out = (float*)d_out;

    float *x, *h, *qkvb, *attb, *ffb, *wt;
    cudaGetSymbolAddress((void**)&x,    g_x);
    cudaGetSymbolAddress((void**)&h,    g_h);
    cudaGetSymbolAddress((void**)&qkvb, g_qkv);
    cudaGetSymbolAddress((void**)&attb, g_att);
    cudaGetSymbolAddress((void**)&ffb,  g_ff);
    cudaGetSymbolAddress((void**)&wt,   g_wt);

    cudaFuncSetAttribute(attn_kernel, cudaFuncAttributeMaxDynamicSharedMemorySize, ATT_SMEM);
    cudaFuncSetAttribute(mma_gemm,    cudaFuncAttributeMaxDynamicSharedMemorySize, GEMM_SMEM);

    int embed_total = Mrows * (Dd / 4);
    embed_kernel<<<(embed_total + 255) / 256, 256>>>(ids, tok, pos, x);

    for (int i = 0; i < Ll; i++) {
        // LN1 -> h (tf32-rounded)
        ln_kernel<<<Mrows, 256>>>(x, n1_s + i * Dd, n1_b + i * Dd, h);

        // qkv: h[8192,768] @ W[768,2304]
        transpose_rna_kernel<<<dim3(QKVN / 32, Dd / 32), 256>>>(qkv_w + (size_t)i * Dd * QKVN, wt, Dd, QKVN);
        mma_gemm<<<dim3(QKVN / 128, Mrows / 128), 256, GEMM_SMEM>>>(
            h, wt, qkv_b + (size_t)i * QKVN, nullptr, qkvb, Dd, QKVN, 0, 0);

        attn_kernel<<<dim3(Ss / 128, Hh, Bb), 128, ATT_SMEM>>>(qkvb, mask, attb);

        // out proj + residual: x = x + att @ W
        transpose_rna_kernel<<<dim3(Dd / 32, Dd / 32), 256>>>(out_w + (size_t)i * Dd * Dd, wt, Dd, Dd);
        mma_gemm<<<dim3(Dd / 128, Mrows / 128), 256, GEMM_SMEM>>>(
            attb, wt, out_b + (size_t)i * Dd, x, x, Dd, Dd, 0, 0);

        // LN2 -> h
        ln_kernel<<<Mrows, 256>>>(x, n2_s + i * Dd, n2_b + i * Dd, h);

        // ff1 + relu (output tf32-rounded: feeds ff2 as A)
        transpose_rna_kernel<<<dim3(DFf / 32, Dd / 32), 256>>>(ff1_w + (size_t)i * Dd * DFf, wt, Dd, DFf);
        mma_gemm<<<dim3(DFf / 128, Mrows / 128), 256, GEMM_SMEM>>>(
            h, wt, ff1_b + (size_t)i * DFf, nullptr, ffb, Dd, DFf, 1, 1);

        // ff2 + residual
        transpose_rna_kernel<<<dim3(Dd / 32, DFf / 32), 256>>>(ff2_w + (size_t)i * DFf * Dd, wt, DFf, Dd);
        mma_gemm<<<dim3(Dd / 128, Mrows / 128), 256, GEMM_SMEM>>>(
            ffb, wt, ff2_b + (size_t)i * Dd, x, x, DFf, Dd, 0, 0);
    }

    pooled_kernel<<<Bb, 256>>>(x, hln_s, hln_b, cls_w, cls_b, out);
}

// round 4
// speedup vs baseline: 2.9518x; 1.5969x over previous
#include <cuda_runtime.h>
#include <cstdint>
#include <math.h>

#define Bb   8
#define Ss   1024
#define Dd   768
#define Hh   12
#define HDd  64
#define Ll   6
#define DFf  3072
#define Cc   2
#define Mrows (Bb*Ss)      /* 8192 */
#define QKVN  (3*Dd)       /* 2304 */
#define LN_EPS 1e-5f

// ---------------- scratch (device globals: allocation-free) ----------------
__device__ float g_x[Mrows*Dd];
__device__ float g_h[Mrows*Dd];
__device__ float g_qkv[Mrows*QKVN];
__device__ float g_att[Mrows*Dd];
__device__ float g_ff[Mrows*DFf];
__device__ float g_wt[DFf*Dd];     // transposed weight scratch (max 3072*768)

// ======================= helpers =======================
__device__ __forceinline__ uint32_t smem_to_u32(const void* p) {
    uint32_t a;
    asm("{ .reg .u64 t; cvta.to.shared.u64 t, %1; cvt.u32.u64 %0, t; }" : "=r"(a) : "l"(p));
    return a;
}
__device__ __forceinline__ float rna_tf32(float v) {
    asm("cvt.rna.tf32.f32 %0, %0;" : "+f"(v));
    return v;
}
#define CP_ASYNC16(dst, src) \
    asm volatile("cp.async.cg.shared.global [%0], [%1], 16;" :: "r"(dst), "l"(src) : "memory")
#define CP_COMMIT() asm volatile("cp.async.commit_group;" ::: "memory")
#define CP_WAIT1()  asm volatile("cp.async.wait_group 1;" ::: "memory")

__device__ __forceinline__ void mma_tf32(float* d, const uint32_t* a, const uint32_t* b) {
    asm volatile(
        "mma.sync.aligned.m16n8k8.row.col.f32.tf32.tf32.f32 "
        "{%0,%1,%2,%3}, {%4,%5,%6,%7}, {%8,%9}, {%0,%1,%2,%3};"
        : "+f"(d[0]), "+f"(d[1]), "+f"(d[2]), "+f"(d[3])
        : "r"(a[0]), "r"(a[1]), "r"(a[2]), "r"(a[3]), "r"(b[0]), "r"(b[1]));
}

// ---------------- embed ----------------
__global__ void embed_kernel(const int* __restrict__ ids,
                             const float* __restrict__ tok,
                             const float* __restrict__ pos,
                             float* __restrict__ x)
{
    const float sc = 27.712812921102035f; // sqrt(768)
    int i = blockIdx.x * blockDim.x + threadIdx.x;
    int total = Mrows * (Dd / 4);
    if (i >= total) return;
    int row = i / (Dd / 4);
    int c4  = i - row * (Dd / 4);
    int s   = row & (Ss - 1);
    int id  = ids[row];
    const float4* t4 = (const float4*)tok;
    const float4* p4 = (const float4*)pos;
    float4 tv = t4[(size_t)id * (Dd/4) + c4];
    float4 pv = p4[(size_t)s  * (Dd/4) + c4];
    float4 o;
    o.x = (tv.x + pv.x) * sc;
    o.y = (tv.y + pv.y) * sc;
    o.z = (tv.z + pv.z) * sc;
    o.w = (tv.w + pv.w) * sc;
    ((float4*)x)[i] = o;
}

// ---------------- block reduce ----------------
__device__ __forceinline__ void blockReduce2(float& a, float& b, float* buf)
{
    #pragma unroll
    for (int o = 16; o; o >>= 1) {
        a += __shfl_xor_sync(0xffffffffu, a, o);
        b += __shfl_xor_sync(0xffffffffu, b, o);
    }
    int w = threadIdx.x >> 5;
    if ((threadIdx.x & 31) == 0) { buf[w] = a; buf[8 + w] = b; }
    __syncthreads();
    a = 0.f; b = 0.f;
    #pragma unroll
    for (int i = 0; i < 8; i++) { a += buf[i]; b += buf[8 + i]; }
    __syncthreads();
}

// ---------------- layernorm (outputs RNA-rounded to tf32: feeds GEMM A) ----
__global__ __launch_bounds__(256)
void ln_kernel(const float* __restrict__ x,
               const float* __restrict__ gs,
               const float* __restrict__ gb,
               float* __restrict__ out)
{
    __shared__ float buf[16];
    int row = blockIdx.x;
    int t = threadIdx.x;
    const float* xr = x + (size_t)row * Dd;
    float v0 = xr[t], v1 = xr[t + 256], v2 = xr[t + 512];
    float sum = v0 + v1 + v2;
    float sq  = v0*v0 + v1*v1 + v2*v2;
    blockReduce2(sum, sq, buf);
    float mean = sum * (1.0f / Dd);
    float var  = sq * (1.0f / Dd) - mean * mean;
    float rstd = rsqrtf(var + LN_EPS);
    float* orow = out + (size_t)row * Dd;
    orow[t]       = rna_tf32((v0 - mean) * rstd * gs[t]       + gb[t]);
    orow[t + 256] = rna_tf32((v1 - mean) * rstd * gs[t + 256] + gb[t + 256]);
    orow[t + 512] = rna_tf32((v2 - mean) * rstd * gs[t + 512] + gb[t + 512]);
}

// ---------------- weight transpose + RNA round: Wt[N,K] = rna(W[K,N]^T) ----
__global__ __launch_bounds__(256)
void transpose_rna_kernel(const float* __restrict__ W, float* __restrict__ Wt, int K, int N)
{
    __shared__ float t[32][33];
    int n0 = blockIdx.x * 32, k0 = blockIdx.y * 32;
    int x = threadIdx.x & 31, y = threadIdx.x >> 5; // 32x8
    #pragma unroll
    for (int i = 0; i < 32; i += 8)
        t[y + i][x] = W[(size_t)(k0 + y + i) * N + n0 + x];
    __syncthreads();
    #pragma unroll
    for (int i = 0; i < 32; i += 8)
        Wt[(size_t)(n0 + y + i) * K + k0 + x] = rna_tf32(t[x][y + i]);
}

// ---------------- tf32 mma.sync GEMM ----------------
// C[M,N] = A[M,K] @ Bt[N,K]^T (+bias)(+res)(relu?)(rnaOut?)
// BM=BN=128, BK=32, 256 threads, warp grid 2x4 (warp tile 64x32),
// 3-stage cp.async pipeline. launch_bounds(256,2) -> <=128 regs, 2 CTAs/SM.
#define TSf (128*36)                 /* floats per tile */
#define GEMM_SMEM (3*2*TSf*4)        /* 110592 bytes */

__global__ __launch_bounds__(256, 2)
void mma_gemm(const float* __restrict__ A, const float* __restrict__ Bt,
              const float* __restrict__ bias, const float* __restrict__ res,
              float* __restrict__ C, int K, int N, int relu, int rnaOut)
{
    extern __shared__ float smf[];
    uint32_t sb = smem_to_u32(smf);
    int tid = threadIdx.x, lane = tid & 31, wid = tid >> 5;
    int warpM = (wid >> 2) * 64, warpN = (wid & 3) * 32;
    int m0 = blockIdx.y * 128, n0 = blockIdx.x * 128;
    const float* Abase = A  + (size_t)m0 * K;
    const float* Bbase = Bt + (size_t)n0 * K;
    int lrow  = tid >> 1;        // 0..127
    int lhalf = (tid & 1) * 16;  // float offset within a 32-float row

    const int KI = K >> 5;

    float acc[4][4][4];
    #pragma unroll
    for (int mt = 0; mt < 4; mt++)
        #pragma unroll
        for (int nt = 0; nt < 4; nt++)
            #pragma unroll
            for (int r = 0; r < 4; r++) acc[mt][nt][r] = 0.f;

    #define ISSUE_STAGE(I) do {                                                  \
        int _st = (I) % 3;                                                       \
        int _k0 = (I) << 5;                                                      \
        uint32_t _dA = sb + (uint32_t)(_st * 2 * TSf + lrow * 36 + lhalf) * 4u;  \
        uint32_t _dB = _dA + (uint32_t)TSf * 4u;                                 \
        const float* _sA = Abase + (size_t)lrow * K + _k0 + lhalf;               \
        const float* _sB = Bbase + (size_t)lrow * K + _k0 + lhalf;               \
        CP_ASYNC16(_dA + 0,  _sA + 0);  CP_ASYNC16(_dB + 0,  _sB + 0);           \
        CP_ASYNC16(_dA + 16, _sA + 4);  CP_ASYNC16(_dB + 16, _sB + 4);           \
        CP_ASYNC16(_dA + 32, _sA + 8);  CP_ASYNC16(_dB + 32, _sB + 8);           \
        CP_ASYNC16(_dA + 48, _sA + 12); CP_ASYNC16(_dB + 48, _sB + 12);          \
    } while (0)

    ISSUE_STAGE(0); CP_COMMIT();
    ISSUE_STAGE(1); CP_COMMIT();

    for (int i = 0; i < KI; i++) {
        CP_WAIT1();
        __syncthreads();
        if (i + 2 < KI) ISSUE_STAGE(i + 2);
        CP_COMMIT();

        const float* As = smf + (i % 3) * 2 * TSf;
        const float* Bs = As + TSf;

        #pragma unroll
        for (int ks = 0; ks < 4; ks++) {
            int kc = ks * 8 + (lane & 3);
            uint32_t a[4][4], b[4][2];
            #pragma unroll
            for (int mt = 0; mt < 4; mt++) {
                int r = warpM + mt * 16 + (lane >> 2);
                a[mt][0] = __float_as_uint(As[r * 36 + kc]);
                a[mt][1] = __float_as_uint(As[(r + 8) * 36 + kc]);
                a[mt][2] = __float_as_uint(As[r * 36 + kc + 4]);
                a[mt][3] = __float_as_uint(As[(r + 8) * 36 + kc + 4]);
            }
            #pragma unroll
            for (int nt = 0; nt < 4; nt++) {
                int n = warpN + nt * 8 + (lane >> 2);
                b[nt][0] = __float_as_uint(Bs[n * 36 + kc]);
                b[nt][1] = __float_as_uint(Bs[n * 36 + kc + 4]);
            }
            #pragma unroll
            for (int mt = 0; mt < 4; mt++)
                #pragma unroll
                for (int nt = 0; nt < 4; nt++)
                    mma_tf32(acc[mt][nt], a[mt], b[nt]);
        }
    }

    // epilogue
    #pragma unroll
    for (int mt = 0; mt < 4; mt++) {
        int r0 = m0 + warpM + mt * 16 + (lane >> 2);
        #pragma unroll
        for (int nt = 0; nt < 4; nt++) {
            int c0 = n0 + warpN + nt * 8 + (lane & 3) * 2;
            float2 bv = *(const float2*)(bias + c0);
            float v0 = acc[mt][nt][0] + bv.x;
            float v1 = acc[mt][nt][1] + bv.y;
            float v2 = acc[mt][nt][2] + bv.x;
            float v3 = acc[mt][nt][3] + bv.y;
            if (res) {
                float2 q1 = *(const float2*)(res + (size_t)r0 * N + c0);
                float2 q2 = *(const float2*)(res + (size_t)(r0 + 8) * N + c0);
                v0 += q1.x; v1 += q1.y; v2 += q2.x; v3 += q2.y;
            }
            if (relu) {
                v0 = fmaxf(v0, 0.f); v1 = fmaxf(v1, 0.f);
                v2 = fmaxf(v2, 0.f); v3 = fmaxf(v3, 0.f);
            }
            if (rnaOut) {
                v0 = rna_tf32(v0); v1 = rna_tf32(v1);
                v2 = rna_tf32(v2); v3 = rna_tf32(v3);
            }
            float2 o1; o1.x = v0; o1.y = v1;
            float2 o2; o2.x = v2; o2.y = v3;
            *(float2*)(C + (size_t)r0 * N + c0)       = o1;
            *(float2*)(C + (size_t)(r0 + 8) * N + c0) = o2;
        }
    }
}

// ---------------- tensor-core flash attention ----------------
// grid (S/128, H, B), 256 threads = 8 warps, warp w owns q-rows [16w,16w+16).
// QK^T and P.V via mma m16n8k8 tf32. Q pre-scaled by 1/8 and RNA-rounded.
#define AT_QP 68
#define AT_KP 68
#define AT_VP 72
#define AT_PP 68
#define ATT_SMEM ((128*AT_QP + 64*AT_KP + 64*AT_VP + 128*AT_PP + 64) * 4)

__global__ __launch_bounds__(256, 2)
void attn_mma_kernel(const float* __restrict__ qkv,
                     const int* __restrict__ mask,
                     float* __restrict__ att)
{
    extern __shared__ float sa[];
    float* Qs = sa;                    // [128][68]
    float* Ks = Qs + 128 * AT_QP;      // [64][68]
    float* Vs = Ks + 64 * AT_KP;       // [64][72]
    float* Ps = Vs + 64 * AT_VP;       // [128][68]
    float* mk = Ps + 128 * AT_PP;      // [64]

    int qb = blockIdx.x, h = blockIdx.y, b = blockIdx.z;
    int tid = threadIdx.x, lane = tid & 31, wid = tid >> 5;
    int rq = lane >> 2, qd = lane & 3;
    int warpM = wid * 16;
    int base_q = b * Ss + qb * 128;

    // load Q tile: scale 1/8 (exact), RNA round
    const float* qsrc = qkv + (size_t)base_q * QKVN + h * 192;
    #pragma unroll
    for (int it = 0; it < 8; it++) {
        int idx = it * 256 + tid;           // 2048 float4 = 128 rows x 16
        int r = idx >> 4, c4 = idx & 15;
        float4 v = *(const float4*)(qsrc + (size_t)r * QKVN + c4 * 4);
        float* dst = Qs + r * AT_QP + c4 * 4;
        dst[0] = rna_tf32(v.x * 0.125f);
        dst[1] = rna_tf32(v.y * 0.125f);
        dst[2] = rna_tf32(v.z * 0.125f);
        dst[3] = rna_tf32(v.w * 0.125f);
    }

    float oacc[8][4];
    #pragma unroll
    for (int nt = 0; nt < 8; nt++)
        #pragma unroll
        for (int r = 0; r < 4; r++) oacc[nt][r] = 0.f;
    float m0 = -1e30f, m1 = -1e30f, l0 = 0.f, l1 = 0.f;

    __syncthreads();   // Q ready

    for (int kt = 0; kt < Ss / 64; kt++) {
        if (kt) __syncthreads();   // previous PV reads of Vs done
        const float* ksrc = qkv + (size_t)(b * Ss + kt * 64) * QKVN + h * 192 + 64;
        const float* vsrc = ksrc + 64;
        #pragma unroll
        for (int it = 0; it < 4; it++) {
            int idx = it * 256 + tid;       // 1024 float4 = 64 rows x 16
            int r = idx >> 4, c4 = idx & 15;
            float4 kv = *(const float4*)(ksrc + (size_t)r * QKVN + c4 * 4);
            float* kd = Ks + r * AT_KP + c4 * 4;
            kd[0] = rna_tf32(kv.x); kd[1] = rna_tf32(kv.y);
            kd[2] = rna_tf32(kv.z); kd[3] = rna_tf32(kv.w);
            float4 vv = *(const float4*)(vsrc + (size_t)r * QKVN + c4 * 4);
            float* vd = Vs + r * AT_VP + c4 * 4;
            vd[0] = rna_tf32(vv.x); vd[1] = rna_tf32(vv.y);
            vd[2] = rna_tf32(vv.z); vd[3] = rna_tf32(vv.w);
        }
        if (tid < 64) mk[tid] = (mask[b * Ss + kt * 64 + tid] != 0) ? 1.f : 0.f;
        __syncthreads();

        // ---- scores: c[nt] = Q(16x64) . K^T (cols nt*8..+8) ----
        float c[8][4];
        #pragma unroll
        for (int nt = 0; nt < 8; nt++)
            #pragma unroll
            for (int r = 0; r < 4; r++) c[nt][r] = 0.f;
        #pragma unroll
        for (int ks = 0; ks < 8; ks++) {
            uint32_t a[4];
            const float* qp = Qs + (warpM + rq) * AT_QP + ks * 8 + qd;
            a[0] = __float_as_uint(qp[0]);
            a[1] = __float_as_uint(qp[8 * AT_QP]);
            a[2] = __float_as_uint(qp[4]);
            a[3] = __float_as_uint(qp[8 * AT_QP + 4]);
            #pragma unroll
            for (int nt = 0; nt < 8; nt++) {
                uint32_t bf[2];
                const float* kp = Ks + (nt * 8 + rq) * AT_KP + ks * 8 + qd;
                bf[0] = __float_as_uint(kp[0]);
                bf[1] = __float_as_uint(kp[4]);
                mma_tf32(c[nt], a, bf);
            }
        }

        // ---- mask + online softmax ----
        float rmax0 = -1e30f, rmax1 = -1e30f;
        #pragma unroll
        for (int nt = 0; nt < 8; nt++) {
            int j0 = nt * 8 + 2 * qd;
            float mk0 = mk[j0], mk1 = mk[j0 + 1];
            if (mk0 != 0.f) { c[nt][0] = -1e9f; c[nt][2] = -1e9f; }
            if (mk1 != 0.f) { c[nt][1] = -1e9f; c[nt][3] = -1e9f; }
            rmax0 = fmaxf(rmax0, fmaxf(c[nt][0], c[nt][1]));
            rmax1 = fmaxf(rmax1, fmaxf(c[nt][2], c[nt][3]));
        }
        rmax0 = fmaxf(rmax0, __shfl_xor_sync(0xffffffffu, rmax0, 1));
        rmax0 = fmaxf(rmax0, __shfl_xor_sync(0xffffffffu, rmax0, 2));
        rmax1 = fmaxf(rmax1, __shfl_xor_sync(0xffffffffu, rmax1, 1));
        rmax1 = fmaxf(rmax1, __shfl_xor_sync(0xffffffffu, rmax1, 2));
        float mn0 = fmaxf(m0, rmax0), mn1 = fmaxf(m1, rmax1);
        float cor0 = __expf(m0 - mn0), cor1 = __expf(m1 - mn1);
        m0 = mn0; m1 = mn1;
        l0 *= cor0; l1 *= cor1;
        #pragma unroll
        for (int nt = 0; nt < 8; nt++) {
            oacc[nt][0] *= cor0; oacc[nt][1] *= cor0;
            oacc[nt][2] *= cor1; oacc[nt][3] *= cor1;
        }
        float ps0 = 0.f, ps1 = 0.f;
        #pragma unroll
        for (int nt = 0; nt < 8; nt++) {
            float p0 = __expf(c[nt][0] - m0);
            float p1 = __expf(c[nt][1] - m0);
            float p2 = __expf(c[nt][2] - m1);
            float p3 = __expf(c[nt][3] - m1);
            ps0 += p0 + p1; ps1 += p2 + p3;
            c[nt][0] = rna_tf32(p0); c[nt][1] = rna_tf32(p1);
            c[nt][2] = rna_tf32(p2); c[nt][3] = rna_tf32(p3);
        }
        l0 += ps0; l1 += ps1;

        // ---- store P (warp-private rows), then P.V ----
        #pragma unroll
        for (int nt = 0; nt < 8; nt++) {
            float* pp = Ps + (warpM + rq) * AT_PP + nt * 8 + 2 * qd;
            float2 w1; w1.x = c[nt][0]; w1.y = c[nt][1];
            float2 w2; w2.x = c[nt][2]; w2.y = c[nt][3];
            *(float2*)pp = w1;
            *(float2*)(pp + 8 * AT_PP) = w2;
        }
        __syncwarp();
        #pragma unroll
        for (int ks = 0; ks < 8; ks++) {
            uint32_t a[4];
            const float* pa = Ps + (warpM + rq) * AT_PP + ks * 8 + qd;
            a[0] = __float_as_uint(pa[0]);
            a[1] = __float_as_uint(pa[8 * AT_PP]);
            a[2] = __float_as_uint(pa[4]);
            a[3] = __float_as_uint(pa[8 * AT_PP + 4]);
            #pragma unroll
            for (int nt = 0; nt < 8; nt++) {
                uint32_t bf[2];
                const float* vp = Vs + (ks * 8 + qd) * AT_VP + nt * 8 + rq;
                bf[0] = __float_as_uint(vp[0]);
                bf[1] = __float_as_uint(vp[4 * AT_VP]);
                mma_tf32(oacc[nt], a, bf);
            }
        }
    }

    // final: full row sums across quad, normalize, write (RNA for next GEMM A)
    l0 += __shfl_xor_sync(0xffffffffu, l0, 1);
    l0 += __shfl_xor_sync(0xffffffffu, l0, 2);
    l1 += __shfl_xor_sync(0xffffffffu, l1, 1);
    l1 += __shfl_xor_sync(0xffffffffu, l1, 2);
    float inv0 = 1.f / l0, inv1 = 1.f / l1;
    int row0 = base_q + warpM + rq;
    #pragma unroll
    for (int nt = 0; nt < 8; nt++) {
        int col = h * HDd + nt * 8 + 2 * qd;
        float2 w1; w1.x = rna_tf32(oacc[nt][0] * inv0); w1.y = rna_tf32(oacc[nt][1] * inv0);
        float2 w2; w2.x = rna_tf32(oacc[nt][2] * inv1); w2.y = rna_tf32(oacc[nt][3] * inv1);
        *(float2*)(att + (size_t)row0 * Dd + col)       = w1;
        *(float2*)(att + (size_t)(row0 + 8) * Dd + col) = w2;
    }
}

// ---------------- pooled LN + classifier ----------------
__global__ __launch_bounds__(256)
void pooled_kernel(const float* __restrict__ x,
                   const float* __restrict__ hs,
                   const float* __restrict__ hb,
                   const float* __restrict__ cw,
                   const float* __restrict__ cb,
                   float* __restrict__ out)
{
    __shared__ float buf[16];
    int b = blockIdx.x;
    int t = threadIdx.x;
    const float* xr = x + (size_t)b * Ss * Dd;
    float v0 = xr[t], v1 = xr[t + 256], v2 = xr[t + 512];
    float sum = v0 + v1 + v2;
    float sq  = v0*v0 + v1*v1 + v2*v2;
    blockReduce2(sum, sq, buf);
    float mean = sum * (1.0f / Dd);
    float var  = sq * (1.0f / Dd) - mean * mean;
    float rstd = rsqrtf(var + LN_EPS);
    float h0 = (v0 - mean) * rstd * hs[t]       + hb[t];
    float h1 = (v1 - mean) * rstd * hs[t + 256] + hb[t + 256];
    float h2 = (v2 - mean) * rstd * hs[t + 512] + hb[t + 512];
    float p0 = h0 * cw[t * 2]     + h1 * cw[(t + 256) * 2]     + h2 * cw[(t + 512) * 2];
    float p1 = h0 * cw[t * 2 + 1] + h1 * cw[(t + 256) * 2 + 1] + h2 * cw[(t + 512) * 2 + 1];
    blockReduce2(p0, p1, buf);
    if (t == 0) {
        out[b * Cc + 0] = p0 + cb[0];
        out[b * Cc + 1] = p1 + cb[1];
    }
}

// ---------------- launcher ----------------
extern "C" void kernel_launch(void* const* d_in, const int* in_sizes, int n_in,
                              void* d_out, int out_size)
{
    const int*   ids    = (const int*)  d_in[0];
    const int*   mask   = (const int*)  d_in[1];
    const float* tok    = (const float*)d_in[2];
    const float* pos    = (const float*)d_in[3];
    const float* qkv_w  = (const float*)d_in[4];
    const float* qkv_b  = (const float*)d_in[5];
    const float* out_w  = (const float*)d_in[6];
    const float* out_b  = (const float*)d_in[7];
    const float* n1_s   = (const float*)d_in[8];
    const float* n1_b   = (const float*)d_in[9];
    const float* ff1_w  = (const float*)d_in[10];
    const float* ff1_b  = (const float*)d_in[11];
    const float* ff2_w  = (const float*)d_in[12];
    const float* ff2_b  = (const float*)d_in[13];
    const float* n2_s   = (const float*)d_in[14];
    const float* n2_b   = (const float*)d_in[15];
    const float* hln_s  = (const float*)d_in[16];
    const float* hln_b  = (const float*)d_in[17];
    const float* cls_w  = (const float*)d_in[18];
    const float* cls_b  = (const float*)d_in[19];
    float* out = (float*)d_out;

    float *x, *h, *qkvb, *attb, *ffb, *wt;
    cudaGetSymbolAddress((void**)&x,    g_x);
    cudaGetSymbolAddress((void**)&h,    g_h);
    cudaGetSymbolAddress((void**)&qkvb, g_qkv);
    cudaGetSymbolAddress((void**)&attb, g_att);
    cudaGetSymbolAddress((void**)&ffb,  g_ff);
    cudaGetSymbolAddress((void**)&wt,   g_wt);

    cudaFuncSetAttribute(attn_mma_kernel, cudaFuncAttributeMaxDynamicSharedMemorySize, ATT_SMEM);
    cudaFuncSetAttribute(mma_gemm,        cudaFuncAttributeMaxDynamicSharedMemorySize, GEMM_SMEM);

    int embed_total = Mrows * (Dd / 4);
    embed_kernel<<<(embed_total + 255) / 256, 256>>>(ids, tok, pos, x);

    for (int i = 0; i < Ll; i++) {
        // LN1 -> h (tf32-rounded)
        ln_kernel<<<Mrows, 256>>>(x, n1_s + i * Dd, n1_b + i * Dd, h);

        // qkv: h[8192,768] @ W[768,2304]
        transpose_rna_kernel<<<dim3(QKVN / 32, Dd / 32), 256>>>(qkv_w + (size_t)i * Dd * QKVN, wt, Dd, QKVN);
        mma_gemm<<<dim3(QKVN / 128, Mrows / 128), 256, GEMM_SMEM>>>(
            h, wt, qkv_b + (size_t)i * QKVN, nullptr, qkvb, Dd, QKVN, 0, 0);

        attn_mma_kernel<<<dim3(Ss / 128, Hh, Bb), 256, ATT_SMEM>>>(qkvb, mask, attb);

        // out proj + residual: x = x + att @ W
        transpose_rna_kernel<<<dim3(Dd / 32, Dd / 32), 256>>>(out_w + (size_t)i * Dd * Dd, wt, Dd, Dd);
        mma_gemm<<<dim3(Dd / 128, Mrows / 128), 256, GEMM_SMEM>>>(
            attb, wt, out_b + (size_t)i * Dd, x, x, Dd, Dd, 0, 0);

        // LN2 -> h
        ln_kernel<<<Mrows, 256>>>(x, n2_s + i * Dd, n2_b + i * Dd, h);

        // ff1 + relu (output tf32-rounded: feeds ff2 as A)
        transpose_rna_kernel<<<dim3(DFf / 32, Dd / 32), 256>>>(ff1_w + (size_t)i * Dd * DFf, wt, Dd, DFf);
        mma_gemm<<<dim3(DFf / 128, Mrows / 128), 256, GEMM_SMEM>>>(
            h, wt, ff1_b + (size_t)i * DFf, nullptr, ffb, Dd, DFf, 1, 1);

        // ff2 + residual
        transpose_rna_kernel<<<dim3(Dd / 32, DFf / 32), 256>>>(ff2_w + (size_t)i * DFf * Dd, wt, DFf, Dd);
        mma_gemm<<<dim3(Dd / 128, Mrows / 128), 256, GEMM_SMEM>>>(
            ffb, wt, ff2_b + (size_t)i * Dd, x, x, DFf, Dd, 0, 0);
    }

    pooled_kernel<<<Bb, 256>>>(x, hln_s, hln_b, cls_w, cls_b, out);
}

// round 5
// speedup vs baseline: 3.0197x; 1.0230x over previous
#include <cuda_runtime.h>
#include <cstdint>
#include <math.h>

#define Bb   8
#define Ss   1024
#define Dd   768
#define Hh   12
#define HDd  64
#define Ll   6
#define DFf  3072
#define Cc   2
#define Mrows (Bb*Ss)      /* 8192 */
#define QKVN  (3*Dd)       /* 2304 */
#define LN_EPS 1e-5f

// ---------------- scratch (device globals: allocation-free) ----------------
__device__ float g_x[Mrows*Dd];
__device__ float g_h[Mrows*Dd];
__device__ float g_qkv[Mrows*QKVN];
__device__ float g_att[Mrows*Dd];
__device__ float g_ff[Mrows*DFf];
__device__ float g_wt[DFf*Dd];     // transposed weight scratch (max 3072*768)

// ======================= helpers =======================
__device__ __forceinline__ uint32_t smem_to_u32(const void* p) {
    uint32_t a;
    asm("{ .reg .u64 t; cvta.to.shared.u64 t, %1; cvt.u32.u64 %0, t; }" : "=r"(a) : "l"(p));
    return a;
}
__device__ __forceinline__ float rna_tf32(float v) {
    asm("cvt.rna.tf32.f32 %0, %0;" : "+f"(v));
    return v;
}
#define CP_ASYNC16(dst, src) \
    asm volatile("cp.async.cg.shared.global [%0], [%1], 16;" :: "r"(dst), "l"(src) : "memory")
#define CP_COMMIT() asm volatile("cp.async.commit_group;" ::: "memory")
#define CP_WAIT0()  asm volatile("cp.async.wait_group 0;" ::: "memory")

__device__ __forceinline__ void mma_tf32(float* d, const uint32_t* a, const uint32_t* b) {
    asm volatile(
        "mma.sync.aligned.m16n8k8.row.col.f32.tf32.tf32.f32 "
        "{%0,%1,%2,%3}, {%4,%5,%6,%7}, {%8,%9}, {%0,%1,%2,%3};"
        : "+f"(d[0]), "+f"(d[1]), "+f"(d[2]), "+f"(d[3])
        : "r"(a[0]), "r"(a[1]), "r"(a[2]), "r"(a[3]), "r"(b[0]), "r"(b[1]));
}

// ---------------- embed ----------------
__global__ void embed_kernel(const int* __restrict__ ids,
                             const float* __restrict__ tok,
                             const float* __restrict__ pos,
                             float* __restrict__ x)
{
    const float sc = 27.712812921102035f; // sqrt(768)
    int i = blockIdx.x * blockDim.x + threadIdx.x;
    int total = Mrows * (Dd / 4);
    if (i >= total) return;
    int row = i / (Dd / 4);
    int c4  = i - row * (Dd / 4);
    int s   = row & (Ss - 1);
    int id  = ids[row];
    const float4* t4 = (const float4*)tok;
    const float4* p4 = (const float4*)pos;
    float4 tv = t4[(size_t)id * (Dd/4) + c4];
    float4 pv = p4[(size_t)s  * (Dd/4) + c4];
    float4 o;
    o.x = (tv.x + pv.x) * sc;
    o.y = (tv.y + pv.y) * sc;
    o.z = (tv.z + pv.z) * sc;
    o.w = (tv.w + pv.w) * sc;
    ((float4*)x)[i] = o;
}

// ---------------- block reduce ----------------
__device__ __forceinline__ void blockReduce2(float& a, float& b, float* buf)
{
    #pragma unroll
    for (int o = 16; o; o >>= 1) {
        a += __shfl_xor_sync(0xffffffffu, a, o);
        b += __shfl_xor_sync(0xffffffffu, b, o);
    }
    int w = threadIdx.x >> 5;
    if ((threadIdx.x & 31) == 0) { buf[w] = a; buf[8 + w] = b; }
    __syncthreads();
    a = 0.f; b = 0.f;
    #pragma unroll
    for (int i = 0; i < 8; i++) { a += buf[i]; b += buf[8 + i]; }
    __syncthreads();
}

// ---------------- layernorm (outputs RNA-rounded to tf32: feeds GEMM A) ----
__global__ __launch_bounds__(256)
void ln_kernel(const float* __restrict__ x,
               const float* __restrict__ gs,
               const float* __restrict__ gb,
               float* __restrict__ out)
{
    __shared__ float buf[16];
    int row = blockIdx.x;
    int t = threadIdx.x;
    const float* xr = x + (size_t)row * Dd;
    float v0 = xr[t], v1 = xr[t + 256], v2 = xr[t + 512];
    float sum = v0 + v1 + v2;
    float sq  = v0*v0 + v1*v1 + v2*v2;
    blockReduce2(sum, sq, buf);
    float mean = sum * (1.0f / Dd);
    float var  = sq * (1.0f / Dd) - mean * mean;
    float rstd = rsqrtf(var + LN_EPS);
    float* orow = out + (size_t)row * Dd;
    orow[t]       = rna_tf32((v0 - mean) * rstd * gs[t]       + gb[t]);
    orow[t + 256] = rna_tf32((v1 - mean) * rstd * gs[t + 256] + gb[t + 256]);
    orow[t + 512] = rna_tf32((v2 - mean) * rstd * gs[t + 512] + gb[t + 512]);
}

// ---------------- weight transpose + RNA round: Wt[N,K] = rna(W[K,N]^T) ----
__global__ __launch_bounds__(256)
void transpose_rna_kernel(const float* __restrict__ W, float* __restrict__ Wt, int K, int N)
{
    __shared__ float t[32][33];
    int n0 = blockIdx.x * 32, k0 = blockIdx.y * 32;
    int x = threadIdx.x & 31, y = threadIdx.x >> 5; // 32x8
    #pragma unroll
    for (int i = 0; i < 32; i += 8)
        t[y + i][x] = W[(size_t)(k0 + y + i) * N + n0 + x];
    __syncthreads();
    #pragma unroll
    for (int i = 0; i < 32; i += 8)
        Wt[(size_t)(n0 + y + i) * K + k0 + x] = rna_tf32(t[x][y + i]);
}

// ---------------- tf32 mma.sync GEMM (v2: float2 pair-k fragments) --------
// C[M,N] = A[M,K] @ Bt[N,K]^T (+bias)(+res)(relu?)(rnaOut?)
// BM=BN=128, BK=32, 256 threads, warp grid 2x4 (warp tile 64x32),
// 2-stage cp.async, rows padded to 40 floats (conflict-free float2 frags).
// k-permutation trick: fragment slots (qd, qd+4) carry natural k (2qd, 2qd+1)
// for BOTH operands -> dot product unchanged, frag loads become LDS.64.
#define GP 40
#define GTSf (128*GP)                /* 5120 floats per tile */
#define GEMM_SMEM (2*2*GTSf*4)       /* 81920 bytes */

template<int K>
__global__ __launch_bounds__(256, 2)
void mma_gemm(const float* __restrict__ A, const float* __restrict__ Bt,
              const float* __restrict__ bias, const float* __restrict__ res,
              float* __restrict__ C, int N, int relu, int rnaOut)
{
    extern __shared__ float smf[];
    uint32_t sb = smem_to_u32(smf);
    int tid = threadIdx.x, lane = tid & 31, wid = tid >> 5;
    int rq = lane >> 2, qd = lane & 3;
    int warpM = (wid >> 2) * 64, warpN = (wid & 3) * 32;
    int m0 = blockIdx.y * 128, n0 = blockIdx.x * 128;
    const float* Abase = A  + (size_t)m0 * K;
    const float* Bbase = Bt + (size_t)n0 * K;
    int lrow  = tid >> 1;        // 0..127
    int lhalf = (tid & 1) * 16;  // float offset within a 32-float row
    constexpr int KI = K >> 5;

    float acc[4][4][4];
    #pragma unroll
    for (int mt = 0; mt < 4; mt++)
        #pragma unroll
        for (int nt = 0; nt < 4; nt++)
            #pragma unroll
            for (int r = 0; r < 4; r++) acc[mt][nt][r] = 0.f;

    #define ISSUE_STAGE(I) do {                                                  \
        int _st = (I) & 1;                                                        \
        int _k0 = (I) << 5;                                                       \
        uint32_t _dA = sb + (uint32_t)(_st * 2 * GTSf + lrow * GP + lhalf) * 4u;  \
        uint32_t _dB = _dA + (uint32_t)GTSf * 4u;                                 \
        const float* _sA = Abase + (size_t)lrow * K + _k0 + lhalf;                \
        const float* _sB = Bbase + (size_t)lrow * K + _k0 + lhalf;                \
        CP_ASYNC16(_dA + 0,  _sA + 0);  CP_ASYNC16(_dB + 0,  _sB + 0);            \
        CP_ASYNC16(_dA + 16, _sA + 4);  CP_ASYNC16(_dB + 16, _sB + 4);            \
        CP_ASYNC16(_dA + 32, _sA + 8);  CP_ASYNC16(_dB + 32, _sB + 8);            \
        CP_ASYNC16(_dA + 48, _sA + 12); CP_ASYNC16(_dB + 48, _sB + 12);           \
    } while (0)

    ISSUE_STAGE(0); CP_COMMIT();

    int aoff = (warpM + rq) * GP + 2 * qd;
    int boff = (warpN + rq) * GP + 2 * qd;

    #pragma unroll 2
    for (int i = 0; i < KI; i++) {
        CP_WAIT0();
        __syncthreads();
        if (i + 1 < KI) { ISSUE_STAGE(i + 1); CP_COMMIT(); }

        const float* As = smf + (i & 1) * 2 * GTSf;
        const float* Bs = As + GTSf;

        // fragment double buffer
        float2 af[2][4][2];
        float2 bf[2][4];
        #pragma unroll
        for (int mt = 0; mt < 4; mt++) {
            af[0][mt][0] = *(const float2*)(As + aoff + mt * 16 * GP);
            af[0][mt][1] = *(const float2*)(As + aoff + mt * 16 * GP + 8 * GP);
        }
        #pragma unroll
        for (int nt = 0; nt < 4; nt++)
            bf[0][nt] = *(const float2*)(Bs + boff + nt * 8 * GP);

        #pragma unroll
        for (int ks = 0; ks < 4; ks++) {
            int cur = ks & 1, nxt = cur ^ 1;
            if (ks < 3) {
                #pragma unroll
                for (int mt = 0; mt < 4; mt++) {
                    af[nxt][mt][0] = *(const float2*)(As + aoff + (ks + 1) * 8 + mt * 16 * GP);
                    af[nxt][mt][1] = *(const float2*)(As + aoff + (ks + 1) * 8 + mt * 16 * GP + 8 * GP);
                }
                #pragma unroll
                for (int nt = 0; nt < 4; nt++)
                    bf[nxt][nt] = *(const float2*)(Bs + boff + (ks + 1) * 8 + nt * 8 * GP);
            }
            #pragma unroll
            for (int mt = 0; mt < 4; mt++) {
                uint32_t a[4];
                a[0] = __float_as_uint(af[cur][mt][0].x);
                a[1] = __float_as_uint(af[cur][mt][1].x);
                a[2] = __float_as_uint(af[cur][mt][0].y);
                a[3] = __float_as_uint(af[cur][mt][1].y);
                #pragma unroll
                for (int nt = 0; nt < 4; nt++) {
                    uint32_t b[2];
                    b[0] = __float_as_uint(bf[cur][nt].x);
                    b[1] = __float_as_uint(bf[cur][nt].y);
                    mma_tf32(acc[mt][nt], a, b);
                }
            }
        }
    }

    // epilogue
    #pragma unroll
    for (int mt = 0; mt < 4; mt++) {
        int r0 = m0 + warpM + mt * 16 + rq;
        #pragma unroll
        for (int nt = 0; nt < 4; nt++) {
            int c0 = n0 + warpN + nt * 8 + qd * 2;
            float2 bv = *(const float2*)(bias + c0);
            float v0 = acc[mt][nt][0] + bv.x;
            float v1 = acc[mt][nt][1] + bv.y;
            float v2 = acc[mt][nt][2] + bv.x;
            float v3 = acc[mt][nt][3] + bv.y;
            if (res) {
                float2 q1 = *(const float2*)(res + (size_t)r0 * N + c0);
                float2 q2 = *(const float2*)(res + (size_t)(r0 + 8) * N + c0);
                v0 += q1.x; v1 += q1.y; v2 += q2.x; v3 += q2.y;
            }
            if (relu) {
                v0 = fmaxf(v0, 0.f); v1 = fmaxf(v1, 0.f);
                v2 = fmaxf(v2, 0.f); v3 = fmaxf(v3, 0.f);
            }
            if (rnaOut) {
                v0 = rna_tf32(v0); v1 = rna_tf32(v1);
                v2 = rna_tf32(v2); v3 = rna_tf32(v3);
            }
            float2 o1; o1.x = v0; o1.y = v1;
            float2 o2; o2.x = v2; o2.y = v3;
            *(float2*)(C + (size_t)r0 * N + c0)       = o1;
            *(float2*)(C + (size_t)(r0 + 8) * N + c0) = o2;
        }
    }
}

// ---------------- tensor-core flash attention (float2 pair-k frags) -------
// grid (S/128, H, B), 256 threads = 8 warps, warp w owns q-rows [16w,16w+16).
#define AT_QP 72
#define AT_KP 72
#define AT_VP 68
#define AT_PP 72
#define ATT_SMEM ((128*AT_QP + 64*AT_KP + 64*AT_VP + 128*AT_PP + 64) * 4)

__global__ __launch_bounds__(256, 2)
void attn_mma_kernel(const float* __restrict__ qkv,
                     const int* __restrict__ mask,
                     float* __restrict__ att)
{
    extern __shared__ float sa[];
    float* Qs = sa;                    // [128][72]
    float* Ks = Qs + 128 * AT_QP;      // [64][72]
    float* Vs = Ks + 64 * AT_KP;       // [64][68]
    float* Ps = Vs + 64 * AT_VP;       // [128][72]
    float* mk = Ps + 128 * AT_PP;      // [64]

    int qb = blockIdx.x, h = blockIdx.y, b = blockIdx.z;
    int tid = threadIdx.x, lane = tid & 31, wid = tid >> 5;
    int rq = lane >> 2, qd = lane & 3;
    int warpM = wid * 16;
    int base_q = b * Ss + qb * 128;

    // load Q tile: scale 1/8 (exact), RNA round
    const float* qsrc = qkv + (size_t)base_q * QKVN + h * 192;
    #pragma unroll
    for (int it = 0; it < 8; it++) {
        int idx = it * 256 + tid;           // 2048 float4 = 128 rows x 16
        int r = idx >> 4, c4 = idx & 15;
        float4 v = *(const float4*)(qsrc + (size_t)r * QKVN + c4 * 4);
        float* dst = Qs + r * AT_QP + c4 * 4;
        dst[0] = rna_tf32(v.x * 0.125f);
        dst[1] = rna_tf32(v.y * 0.125f);
        dst[2] = rna_tf32(v.z * 0.125f);
        dst[3] = rna_tf32(v.w * 0.125f);
    }

    float oacc[8][4];
    #pragma unroll
    for (int nt = 0; nt < 8; nt++)
        #pragma unroll
        for (int r = 0; r < 4; r++) oacc[nt][r] = 0.f;
    float m0 = -1e30f, m1 = -1e30f, l0 = 0.f, l1 = 0.f;

    __syncthreads();   // Q ready

    for (int kt = 0; kt < Ss / 64; kt++) {
        if (kt) __syncthreads();   // previous PV reads of Vs done
        const float* ksrc = qkv + (size_t)(b * Ss + kt * 64) * QKVN + h * 192 + 64;
        const float* vsrc = ksrc + 64;
        #pragma unroll
        for (int it = 0; it < 4; it++) {
            int idx = it * 256 + tid;       // 1024 float4 = 64 rows x 16
            int r = idx >> 4, c4 = idx & 15;
            float4 kv = *(const float4*)(ksrc + (size_t)r * QKVN + c4 * 4);
            float* kd = Ks + r * AT_KP + c4 * 4;
            kd[0] = rna_tf32(kv.x); kd[1] = rna_tf32(kv.y);
            kd[2] = rna_tf32(kv.z); kd[3] = rna_tf32(kv.w);
            float4 vv = *(const float4*)(vsrc + (size_t)r * QKVN + c4 * 4);
            float* vd = Vs + r * AT_VP + c4 * 4;
            vd[0] = rna_tf32(vv.x); vd[1] = rna_tf32(vv.y);
            vd[2] = rna_tf32(vv.z); vd[3] = rna_tf32(vv.w);
        }
        if (tid < 64) mk[tid] = (mask[b * Ss + kt * 64 + tid] != 0) ? 1.f : 0.f;
        __syncthreads();

        // ---- scores: Q(16x64) . K^T, pair-k fragments ----
        float c[8][4];
        #pragma unroll
        for (int nt = 0; nt < 8; nt++)
            #pragma unroll
            for (int r = 0; r < 4; r++) c[nt][r] = 0.f;
        #pragma unroll
        for (int ks = 0; ks < 8; ks++) {
            const float* qp = Qs + (warpM + rq) * AT_QP + ks * 8 + 2 * qd;
            float2 q0 = *(const float2*)qp;
            float2 q1 = *(const float2*)(qp + 8 * AT_QP);
            uint32_t a[4];
            a[0] = __float_as_uint(q0.x);
            a[1] = __float_as_uint(q1.x);
            a[2] = __float_as_uint(q0.y);
            a[3] = __float_as_uint(q1.y);
            #pragma unroll
            for (int nt = 0; nt < 8; nt++) {
                float2 kk = *(const float2*)(Ks + (nt * 8 + rq) * AT_KP + ks * 8 + 2 * qd);
                uint32_t bfr[2];
                bfr[0] = __float_as_uint(kk.x);
                bfr[1] = __float_as_uint(kk.y);
                mma_tf32(c[nt], a, bfr);
            }
        }

        // ---- mask + online softmax ----
        float rmax0 = -1e30f, rmax1 = -1e30f;
        #pragma unroll
        for (int nt = 0; nt < 8; nt++) {
            int j0 = nt * 8 + 2 * qd;
            float mk0 = mk[j0], mk1 = mk[j0 + 1];
            if (mk0 != 0.f) { c[nt][0] = -1e9f; c[nt][2] = -1e9f; }
            if (mk1 != 0.f) { c[nt][1] = -1e9f; c[nt][3] = -1e9f; }
            rmax0 = fmaxf(rmax0, fmaxf(c[nt][0], c[nt][1]));
            rmax1 = fmaxf(rmax1, fmaxf(c[nt][2], c[nt][3]));
        }
        rmax0 = fmaxf(rmax0, __shfl_xor_sync(0xffffffffu, rmax0, 1));
        rmax0 = fmaxf(rmax0, __shfl_xor_sync(0xffffffffu, rmax0, 2));
        rmax1 = fmaxf(rmax1, __shfl_xor_sync(0xffffffffu, rmax1, 1));
        rmax1 = fmaxf(rmax1, __shfl_xor_sync(0xffffffffu, rmax1, 2));
        float mn0 = fmaxf(m0, rmax0), mn1 = fmaxf(m1, rmax1);
        float cor0 = __expf(m0 - mn0), cor1 = __expf(m1 - mn1);
        m0 = mn0; m1 = mn1;
        l0 *= cor0; l1 *= cor1;
        #pragma unroll
        for (int nt = 0; nt < 8; nt++) {
            oacc[nt][0] *= cor0; oacc[nt][1] *= cor0;
            oacc[nt][2] *= cor1; oacc[nt][3] *= cor1;
        }
        float ps0 = 0.f, ps1 = 0.f;
        #pragma unroll
        for (int nt = 0; nt < 8; nt++) {
            float p0 = __expf(c[nt][0] - m0);
            float p1 = __expf(c[nt][1] - m0);
            float p2 = __expf(c[nt][2] - m1);
            float p3 = __expf(c[nt][3] - m1);
            ps0 += p0 + p1; ps1 += p2 + p3;
            c[nt][0] = rna_tf32(p0); c[nt][1] = rna_tf32(p1);
            c[nt][2] = rna_tf32(p2); c[nt][3] = rna_tf32(p3);
        }
        l0 += ps0; l1 += ps1;

        // ---- store P (warp-private rows), then P.V with pair-k frags ----
        #pragma unroll
        for (int nt = 0; nt < 8; nt++) {
            float* pp = Ps + (warpM + rq) * AT_PP + nt * 8 + 2 * qd;
            float2 w1; w1.x = c[nt][0]; w1.y = c[nt][1];
            float2 w2; w2.x = c[nt][2]; w2.y = c[nt][3];
            *(float2*)pp = w1;
            *(float2*)(pp + 8 * AT_PP) = w2;
        }
        __syncwarp();
        #pragma unroll
        for (int ks = 0; ks < 8; ks++) {
            const float* pa = Ps + (warpM + rq) * AT_PP + ks * 8 + 2 * qd;
            float2 p0 = *(const float2*)pa;
            float2 p1 = *(const float2*)(pa + 8 * AT_PP);
            uint32_t a[4];
            a[0] = __float_as_uint(p0.x);
            a[1] = __float_as_uint(p1.x);
            a[2] = __float_as_uint(p0.y);
            a[3] = __float_as_uint(p1.y);
            #pragma unroll
            for (int nt = 0; nt < 8; nt++) {
                // V rows (natural j = ks*8 + 2qd, +1) to match pair-k order
                const float* vp = Vs + (ks * 8 + 2 * qd) * AT_VP + nt * 8 + rq;
                uint32_t bfr[2];
                bfr[0] = __float_as_uint(vp[0]);
                bfr[1] = __float_as_uint(vp[AT_VP]);
                mma_tf32(oacc[nt], a, bfr);
            }
        }
    }

    // final: row sums across quad, normalize, write (RNA for next GEMM A)
    l0 += __shfl_xor_sync(0xffffffffu, l0, 1);
    l0 += __shfl_xor_sync(0xffffffffu, l0, 2);
    l1 += __shfl_xor_sync(0xffffffffu, l1, 1);
    l1 += __shfl_xor_sync(0xffffffffu, l1, 2);
    float inv0 = 1.f / l0, inv1 = 1.f / l1;
    int row0 = base_q + warpM + rq;
    #pragma unroll
    for (int nt = 0; nt < 8; nt++) {
        int col = h * HDd + nt * 8 + 2 * qd;
        float2 w1; w1.x = rna_tf32(oacc[nt][0] * inv0); w1.y = rna_tf32(oacc[nt][1] * inv0);
        float2 w2; w2.x = rna_tf32(oacc[nt][2] * inv1); w2.y = rna_tf32(oacc[nt][3] * inv1);
        *(float2*)(att + (size_t)row0 * Dd + col)       = w1;
        *(float2*)(att + (size_t)(row0 + 8) * Dd + col) = w2;
    }
}

// ---------------- pooled LN + classifier ----------------
__global__ __launch_bounds__(256)
void pooled_kernel(const float* __restrict__ x,
                   const float* __restrict__ hs,
                   const float* __restrict__ hb,
                   const float* __restrict__ cw,
                   const float* __restrict__ cb,
                   float* __restrict__ out)
{
    __shared__ float buf[16];
    int b = blockIdx.x;
    int t = threadIdx.x;
    const float* xr = x + (size_t)b * Ss * Dd;
    float v0 = xr[t], v1 = xr[t + 256], v2 = xr[t + 512];
    float sum = v0 + v1 + v2;
    float sq  = v0*v0 + v1*v1 + v2*v2;
    blockReduce2(sum, sq, buf);
    float mean = sum * (1.0f / Dd);
    float var  = sq * (1.0f / Dd) - mean * mean;
    float rstd = rsqrtf(var + LN_EPS);
    float h0 = (v0 - mean) * rstd * hs[t]       + hb[t];
    float h1 = (v1 - mean) * rstd * hs[t + 256] + hb[t + 256];
    float h2 = (v2 - mean) * rstd * hs[t + 512] + hb[t + 512];
    float p0 = h0 * cw[t * 2]     + h1 * cw[(t + 256) * 2]     + h2 * cw[(t + 512) * 2];
    float p1 = h0 * cw[t * 2 + 1] + h1 * cw[(t + 256) * 2 + 1] + h2 * cw[(t + 512) * 2 + 1];
    blockReduce2(p0, p1, buf);
    if (t == 0) {
        out[b * Cc + 0] = p0 + cb[0];
        out[b * Cc + 1] = p1 + cb[1];
    }
}

// ---------------- launcher ----------------
extern "C" void kernel_launch(void* const* d_in, const int* in_sizes, int n_in,
                              void* d_out, int out_size)
{
    const int*   ids    = (const int*)  d_in[0];
    const int*   mask   = (const int*)  d_in[1];
    const float* tok    = (const float*)d_in[2];
    const float* pos    = (const float*)d_in[3];
    const float* qkv_w  = (const float*)d_in[4];
    const float* qkv_b  = (const float*)d_in[5];
    const float* out_w  = (const float*)d_in[6];
    const float* out_b  = (const float*)d_in[7];
    const float* n1_s   = (const float*)d_in[8];
    const float* n1_b   = (const float*)d_in[9];
    const float* ff1_w  = (const float*)d_in[10];
    const float* ff1_b  = (const float*)d_in[11];
    const float* ff2_w  = (const float*)d_in[12];
    const float* ff2_b  = (const float*)d_in[13];
    const float* n2_s   = (const float*)d_in[14];
    const float* n2_b   = (const float*)d_in[15];
    const float* hln_s  = (const float*)d_in[16];
    const float* hln_b  = (const float*)d_in[17];
    const float* cls_w  = (const float*)d_in[18];
    const float* cls_b  = (const float*)d_in[19];
    float* out = (float*)d_out;

    float *x, *h, *qkvb, *attb, *ffb, *wt;
    cudaGetSymbolAddress((void**)&x,    g_x);
    cudaGetSymbolAddress((void**)&h,    g_h);
    cudaGetSymbolAddress((void**)&qkvb, g_qkv);
    cudaGetSymbolAddress((void**)&attb, g_att);
    cudaGetSymbolAddress((void**)&ffb,  g_ff);
    cudaGetSymbolAddress((void**)&wt,   g_wt);

    cudaFuncSetAttribute(attn_mma_kernel, cudaFuncAttributeMaxDynamicSharedMemorySize, ATT_SMEM);
    cudaFuncSetAttribute(mma_gemm<768>,   cudaFuncAttributeMaxDynamicSharedMemorySize, GEMM_SMEM);
    cudaFuncSetAttribute(mma_gemm<3072>,  cudaFuncAttributeMaxDynamicSharedMemorySize, GEMM_SMEM);

    int embed_total = Mrows * (Dd / 4);
    embed_kernel<<<(embed_total + 255) / 256, 256>>>(ids, tok, pos, x);

    for (int i = 0; i < Ll; i++) {
        // LN1 -> h (tf32-rounded)
        ln_kernel<<<Mrows, 256>>>(x, n1_s + i * Dd, n1_b + i * Dd, h);

        // qkv: h[8192,768] @ W[768,2304]
        transpose_rna_kernel<<<dim3(QKVN / 32, Dd / 32), 256>>>(qkv_w + (size_t)i * Dd * QKVN, wt, Dd, QKVN);
        mma_gemm<768><<<dim3(QKVN / 128, Mrows / 128), 256, GEMM_SMEM>>>(
            h, wt, qkv_b + (size_t)i * QKVN, nullptr, qkvb, QKVN, 0, 0);

        attn_mma_kernel<<<dim3(Ss / 128, Hh, Bb), 256, ATT_SMEM>>>(qkvb, mask, attb);

        // out proj + residual: x = x + att @ W
        transpose_rna_kernel<<<dim3(Dd / 32, Dd / 32), 256>>>(out_w + (size_t)i * Dd * Dd, wt, Dd, Dd);
        mma_gemm<768><<<dim3(Dd / 128, Mrows / 128), 256, GEMM_SMEM>>>(
            attb, wt, out_b + (size_t)i * Dd, x, x, Dd, 0, 0);

        // LN2 -> h
        ln_kernel<<<Mrows, 256>>>(x, n2_s + i * Dd, n2_b + i * Dd, h);

        // ff1 + relu (output tf32-rounded: feeds ff2 as A)
        transpose_rna_kernel<<<dim3(DFf / 32, Dd / 32), 256>>>(ff1_w + (size_t)i * Dd * DFf, wt, Dd, DFf);
        mma_gemm<768><<<dim3(DFf / 128, Mrows / 128), 256, GEMM_SMEM>>>(
            h, wt, ff1_b + (size_t)i * DFf, nullptr, ffb, DFf, 1, 1);

        // ff2 + residual
        transpose_rna_kernel<<<dim3(Dd / 32, DFf / 32), 256>>>(ff2_w + (size_t)i * DFf * Dd, wt, DFf, Dd);
        mma_gemm<3072><<<dim3(Dd / 128, Mrows / 128), 256, GEMM_SMEM>>>(
            ffb, wt, ff2_b + (size_t)i * Dd, x, x, Dd, 0, 0);
    }

    pooled_kernel<<<Bb, 256>>>(x, hln_s, hln_b, cls_w, cls_b, out);
}